// round 4
// baseline (speedup 1.0000x reference)
#include <cuda_runtime.h>
#include <cstdint>

#define NN 100000
#define EE 3200000
#define DD 64
#define WSZ 8                                 // edges per window
#define NWIN ((EE + WSZ - 1) / WSZ)           // 400000
#define SCAN_B 256
#define NBLK ((NN + SCAN_B - 1) / SCAN_B)     // 391

// Static scratch (no allocation allowed)
__device__ int   g_deg[NN];
__device__ float g_dinv[NN];
__device__ int   g_ptr[NN + 1];
__device__ int   g_bsum[NBLK];
__device__ int   g_boff[NBLK];
__device__ int   g_fill[NN];
__device__ __align__(16) int4  g_csr[EE];     // {src, tgt, bitcast(norm), 0}, sorted by tgt
__device__ __align__(16) float g_xa[NN * DD];
__device__ __align__(16) float g_xb[NN * DD];

// ---------------- preprocessing ----------------

__global__ void zero_counts_kernel() {
    int i = blockIdx.x * blockDim.x + threadIdx.x;
    if (i < NN) { g_deg[i] = 0; g_fill[i] = 0; }
}

__global__ void count_deg_kernel(const int* __restrict__ col32) {
    int e = blockIdx.x * blockDim.x + threadIdx.x;
    if (e < EE) {
        int c = col32[e];
        if (c >= 0 && c < NN) atomicAdd(&g_deg[c], 1);
    }
}

__global__ void dinv_kernel() {
    int i = blockIdx.x * blockDim.x + threadIdx.x;
    if (i < NN) {
        int d = g_deg[i];
        g_dinv[i] = (d > 0) ? rsqrtf((float)d) : 0.0f;
    }
}

__global__ void scan1_kernel() {
    __shared__ int s[SCAN_B];
    int tid = threadIdx.x;
    int gid = blockIdx.x * SCAN_B + tid;
    int v = (gid < NN) ? g_deg[gid] : 0;
    s[tid] = v;
    __syncthreads();
    #pragma unroll
    for (int off = 1; off < SCAN_B; off <<= 1) {
        int t = (tid >= off) ? s[tid - off] : 0;
        __syncthreads();
        s[tid] += t;
        __syncthreads();
    }
    if (gid < NN) g_ptr[gid] = s[tid] - v;
    if (tid == SCAN_B - 1) g_bsum[blockIdx.x] = s[tid];
}

__global__ void scan2_kernel() {
    __shared__ int s[512];
    int tid = threadIdx.x;
    int v = (tid < NBLK) ? g_bsum[tid] : 0;
    s[tid] = v;
    __syncthreads();
    #pragma unroll
    for (int off = 1; off < 512; off <<= 1) {
        int t = (tid >= off) ? s[tid - off] : 0;
        __syncthreads();
        s[tid] += t;
        __syncthreads();
    }
    if (tid < NBLK) g_boff[tid] = s[tid] - v;
    if (tid == NBLK - 1) g_ptr[NN] = s[tid];
}

__global__ void scan3_kernel() {
    int gid = blockIdx.x * SCAN_B + threadIdx.x;
    if (gid < NN) g_ptr[gid] += g_boff[blockIdx.x];
}

__global__ void fill_kernel(const int* __restrict__ row32,
                            const int* __restrict__ col32) {
    int e = blockIdx.x * blockDim.x + threadIdx.x;
    if (e < EE) {
        int r = row32[e];
        int c = col32[e];
        if (r >= 0 && r < NN && c >= 0 && c < NN) {
            float nrm = g_dinv[r] * g_dinv[c];
            int pos = atomicAdd(&g_fill[c], 1);
            g_csr[g_ptr[c] + pos] = make_int4(r, c, __float_as_int(nrm), 0);
        }
    }
}

__global__ void init_kernel(const float* __restrict__ emb, float* __restrict__ out) {
    int i = blockIdx.x * blockDim.x + threadIdx.x;
    if (i < NN * DD) out[i] = emb[i];
}

__global__ void zero_buf_kernel(float* __restrict__ p) {
    int i = blockIdx.x * blockDim.x + threadIdx.x;
    if (i < NN * DD) p[i] = 0.0f;
}

// ---------------- run-collapsed scatter over sorted edges ----------------
// Thread = (window w of WSZ consecutive sorted edges, chunk c in 0..15).
// Lanes 0-15 of a warp: window w0 chunks 0-15 ; lanes 16-31: window w0+1.
// Accumulate float4 in registers while target unchanged; RED on run boundary.
__device__ __forceinline__ void red4(float* dst, float4 v) {
    asm volatile("red.global.add.v4.f32 [%0], {%1,%2,%3,%4};"
                 :: "l"(dst), "f"(v.x), "f"(v.y), "f"(v.z), "f"(v.w)
                 : "memory");
}

__global__ __launch_bounds__(256) void scatter_kernel(const float* __restrict__ xin,
                                                      float* __restrict__ xout) {
    int gid = blockIdx.x * blockDim.x + threadIdx.x;
    int c = gid & 15;
    int w = gid >> 4;
    if (w >= NWIN) return;
    int base = w * WSZ;

    float4 acc = make_float4(0.f, 0.f, 0.f, 0.f);
    int cur = -1;

    #pragma unroll
    for (int jj = 0; jj < WSZ; jj++) {
        int j = base + jj;
        if (j < EE) {
            int4 ed = __ldg(&g_csr[j]);
            float nrm = __int_as_float(ed.z);
            if (ed.y != cur) {
                if (cur >= 0)
                    red4(reinterpret_cast<float*>(
                         reinterpret_cast<float4*>(xout + (size_t)cur * DD) + c), acc);
                acc = make_float4(0.f, 0.f, 0.f, 0.f);
                cur = ed.y;
            }
            float4 v = __ldg(reinterpret_cast<const float4*>(xin + (size_t)ed.x * DD) + c);
            acc.x = fmaf(nrm, v.x, acc.x);
            acc.y = fmaf(nrm, v.y, acc.y);
            acc.z = fmaf(nrm, v.z, acc.z);
            acc.w = fmaf(nrm, v.w, acc.w);
        }
    }
    if (cur >= 0)
        red4(reinterpret_cast<float*>(
             reinterpret_cast<float4*>(xout + (size_t)cur * DD) + c), acc);
}

// out += x
__global__ void accum_kernel(float* __restrict__ out, const float* __restrict__ x) {
    int i = blockIdx.x * blockDim.x + threadIdx.x;
    if (i < NN * DD) out[i] += x[i];
}

// out *= s
__global__ void scale_kernel(float* __restrict__ out, float s) {
    int i = blockIdx.x * blockDim.x + threadIdx.x;
    if (i < NN * DD) out[i] *= s;
}

// ---------------- launch ----------------

extern "C" void kernel_launch(void* const* d_in, const int* in_sizes, int n_in,
                              void* d_out, int out_size) {
    const float* emb = (const float*)d_in[0];
    const int* edge  = (const int*)d_in[1];   // [2, EE] int32
    const int* row32 = edge;
    const int* col32 = edge + EE;
    float* out = (float*)d_out;

    const int T = 256;
    int gN  = (NN + T - 1) / T;
    int gE  = (EE + T - 1) / T;
    int gND = (NN * DD + T - 1) / T;
    int gS  = (int)(((long long)NWIN * 16 + T - 1) / T);

    // CSR (target-sorted edge list) build
    zero_counts_kernel<<<gN, T>>>();
    count_deg_kernel<<<gE, T>>>(col32);
    dinv_kernel<<<gN, T>>>();
    scan1_kernel<<<NBLK, SCAN_B>>>();
    scan2_kernel<<<1, 512>>>();
    scan3_kernel<<<NBLK, SCAN_B>>>();
    fill_kernel<<<gE, T>>>(row32, col32);

    init_kernel<<<gND, T>>>(emb, out);

    // Layer 1: emb -> xa ; out += xa
    zero_buf_kernel<<<gND, T>>>(g_xa);
    scatter_kernel<<<gS, T>>>(emb, g_xa);
    accum_kernel<<<gND, T>>>(out, g_xa);

    // Layer 2: xa -> xb ; out += xb
    zero_buf_kernel<<<gND, T>>>(g_xb);
    scatter_kernel<<<gS, T>>>(g_xa, g_xb);
    accum_kernel<<<gND, T>>>(out, g_xb);

    // Layer 3: xb -> out directly (out holds x0+x1+x2, atomics add x3), then /4
    scatter_kernel<<<gS, T>>>(g_xb, out);
    scale_kernel<<<gND, T>>>(out, 0.25f);
}